// round 3
// baseline (speedup 1.0000x reference)
#include <cuda_runtime.h>
#include <stdint.h>
#include <math.h>

// Fixed shapes
#define BDIM   32
#define CDIM   64
#define HW     4096                 // 64*64
#define KCODES 512
#define NPTS   (BDIM*HW)            // 131072
#define NQ     (NPTS*CDIM)          // 8388608
// Output layout: [loss(1) | quantized(NQ) | perplexity(1) | indices(NPTS)]
#define QOFF   1
#define POFF   (1+NQ)
#define IOFF   (2+NQ)

#define TPB    256
#define NCTA   (NPTS/TPB)           // 512 CTAs

// smem: sE[64][512] + se2h[512] + shist[512]
#define SMEM_BYTES ((CDIM*KCODES + 2*KCODES)*4)   // 135168 B

__device__ float g_loss_part[NCTA];
__device__ int   g_hist_part[NCTA*KCODES];

__global__ void __launch_bounds__(TPB, 1)
vq_main(const float* __restrict__ x, const float* __restrict__ emb,
        float* __restrict__ out) {
    extern __shared__ float sm[];
    float* sE    = sm;                       // [c][k], k contiguous
    float* se2h  = sm + CDIM*KCODES;         // 0.5*||e_k||^2
    int*   shist = (int*)(se2h + KCODES);
    __shared__ float wsum[8];

    const int tid = threadIdx.x;

    uint32_t sbase;
    asm("{ .reg .u64 t; cvta.to.shared.u64 t, %1; cvt.u32.u64 %0, t; }"
        : "=r"(sbase) : "l"(sm));

    // Stage embeddings [64,512] -> smem, float4 coalesced
    {
        const float4* e4  = (const float4*)emb;
        float4*       sE4 = (float4*)sE;
        #pragma unroll
        for (int i = 0; i < (CDIM*KCODES/4)/TPB; i++)
            sE4[tid + i*TPB] = e4[tid + i*TPB];
    }
    shist[tid] = 0;
    shist[tid + TPB] = 0;
    __syncthreads();

    // 0.5*||e_k||^2 (column reads: distinct banks across lanes)
    #pragma unroll
    for (int kk = tid; kk < KCODES; kk += TPB) {
        float s = 0.0f;
        #pragma unroll 8
        for (int c = 0; c < CDIM; c++) {
            float v = sE[c*KCODES + kk];
            s = fmaf(v, v, s);
        }
        se2h[kk] = 0.5f * s;
    }
    __syncthreads();

    // One point per thread; consecutive tid -> consecutive w (coalesced)
    const int p  = blockIdx.x * TPB + tid;
    const int b  = p >> 12;
    const int hw = p & (HW - 1);
    const float* xp = x + (size_t)b * CDIM * HW + hw;

    float z[CDIM];
    #pragma unroll
    for (int c = 0; c < CDIM; c++) z[c] = xp[c * HW];

    // argmin_k 0.5*||e_k||^2 - z.e_k   (8 codes per tile, 4 f32x2 chains)
    float best = 3.4e38f;
    int   bi   = 0;
    #pragma unroll 1
    for (int k0 = 0; k0 < KCODES; k0 += 8) {
        unsigned long long a0 = 0, a1 = 0, a2 = 0, a3 = 0;
        uint32_t ea = sbase + k0 * 4;
        #pragma unroll
        for (int c = 0; c < CDIM; c++) {
            unsigned long long zz, e0, e1, e2, e3;
            asm("mov.b64 %0, {%1, %1};" : "=l"(zz) : "r"(__float_as_uint(z[c])));
            asm("ld.shared.v2.u64 {%0, %1}, [%2];"      : "=l"(e0), "=l"(e1) : "r"(ea));
            asm("ld.shared.v2.u64 {%0, %1}, [%2 + 16];" : "=l"(e2), "=l"(e3) : "r"(ea));
            asm("fma.rn.f32x2 %0, %1, %2, %0;" : "+l"(a0) : "l"(zz), "l"(e0));
            asm("fma.rn.f32x2 %0, %1, %2, %0;" : "+l"(a1) : "l"(zz), "l"(e1));
            asm("fma.rn.f32x2 %0, %1, %2, %0;" : "+l"(a2) : "l"(zz), "l"(e2));
            asm("fma.rn.f32x2 %0, %1, %2, %0;" : "+l"(a3) : "l"(zz), "l"(e3));
            ea += KCODES * 4;
        }
        unsigned int u[8];
        asm("mov.b64 {%0, %1}, %2;" : "=r"(u[0]), "=r"(u[1]) : "l"(a0));
        asm("mov.b64 {%0, %1}, %2;" : "=r"(u[2]), "=r"(u[3]) : "l"(a1));
        asm("mov.b64 {%0, %1}, %2;" : "=r"(u[4]), "=r"(u[5]) : "l"(a2));
        asm("mov.b64 {%0, %1}, %2;" : "=r"(u[6]), "=r"(u[7]) : "l"(a3));
        #pragma unroll
        for (int j = 0; j < 8; j++) {
            float dist = se2h[k0 + j] - __uint_as_float(u[j]);
            if (dist < best) { best = dist; bi = k0 + j; }  // strict <: first argmin
        }
    }

    out[IOFF + p] = (float)bi;
    atomicAdd(&shist[bi], 1);

    // Gather code vector, write quantized (coalesced), accumulate (q-z)^2
    float lsum = 0.0f;
    float* oq = out + QOFF + (size_t)b * CDIM * HW + hw;
    #pragma unroll
    for (int c = 0; c < CDIM; c++) {
        float q  = sE[c*KCODES + bi];
        float df = q - z[c];
        lsum = fmaf(df, df, lsum);
        oq[c * HW] = q;
    }

    // Block-reduce loss partial (deterministic; per-CTA slot)
    #pragma unroll
    for (int o = 16; o > 0; o >>= 1)
        lsum += __shfl_down_sync(0xffffffffu, lsum, o);
    if ((tid & 31) == 0) wsum[tid >> 5] = lsum;
    __syncthreads();   // also orders shist atomics before flush
    if (tid < 8) {
        float v = wsum[tid];
        #pragma unroll
        for (int o = 4; o > 0; o >>= 1)
            v += __shfl_down_sync(0xffu, v, o);
        if (tid == 0) g_loss_part[blockIdx.x] = v;
    }

    // Flush per-CTA histogram (plain stores, no atomics)
    g_hist_part[blockIdx.x*KCODES + tid]       = shist[tid];
    g_hist_part[blockIdx.x*KCODES + tid + TPB] = shist[tid + TPB];
}

__global__ void __launch_bounds__(KCODES)
vq_final(float* __restrict__ out) {
    __shared__ float ws[16];
    __shared__ float ws2[16];
    const int t = threadIdx.x;   // 512

    // Sum histogram partials for code t (coalesced across threads)
    int cnt = 0;
    #pragma unroll 8
    for (int cta = 0; cta < NCTA; cta++)
        cnt += g_hist_part[cta*KCODES + t];

    // Entropy term
    float pr = (float)cnt * (1.0f / (float)NPTS);
    float v  = pr * logf(pr + 1e-10f);
    // Loss partial (one per CTA; 512 slots == 512 threads)
    float lp = g_loss_part[t < NCTA ? t : 0] * (t < NCTA ? 1.0f : 0.0f);

    #pragma unroll
    for (int o = 16; o > 0; o >>= 1) {
        v  += __shfl_down_sync(0xffffffffu, v,  o);
        lp += __shfl_down_sync(0xffffffffu, lp, o);
    }
    if ((t & 31) == 0) { ws[t >> 5] = v; ws2[t >> 5] = lp; }
    __syncthreads();
    if (t < 16) {
        float s  = ws[t];
        float ls = ws2[t];
        #pragma unroll
        for (int o = 8; o > 0; o >>= 1) {
            s  += __shfl_down_sync(0xffffu, s,  o);
            ls += __shfl_down_sync(0xffffu, ls, o);
        }
        if (t == 0) {
            // loss = q_latent + 0.25*e_latent; both equal mean((q-z)^2)
            out[0]    = ls * (1.25f / (float)NQ);
            out[POFF] = expf(-s);
        }
    }
}

extern "C" void kernel_launch(void* const* d_in, const int* in_sizes, int n_in,
                              void* d_out, int out_size) {
    const float* x   = (const float*)d_in[0];
    const float* emb = (const float*)d_in[1];
    float* out = (float*)d_out;

    cudaFuncSetAttribute(vq_main, cudaFuncAttributeMaxDynamicSharedMemorySize,
                         SMEM_BYTES);

    vq_main<<<NCTA, TPB, SMEM_BYTES>>>(x, emb, out);
    vq_final<<<1, KCODES>>>(out);
}